// round 6
// baseline (speedup 1.0000x reference)
#include <cuda_runtime.h>
#include <math_constants.h>

#define W      8192
#define ROWS   4096      // 16 * 1 * 256
#define NLAG   4096      // W / 2
#define TPB    512
#define EPT    16        // elements per thread (TPB * EPT == W)
#define NWARP  (TPB / 32)
#define WCAP   16        // per-warp candidate capacity (expected ~3-6 used)

__device__ __forceinline__ bool better(float v, int i, float v2, int i2) {
    return (v > v2) || (v == v2 && i < i2);
}

__device__ __forceinline__ void ins3(float v, int i,
                                     float& s0, int& i0,
                                     float& s1, int& i1,
                                     float& s2, int& i2) {
    if (better(v, i, s0, i0)) {
        s2 = s1; i2 = i1;
        s1 = s0; i1 = i0;
        s0 = v;  i0 = i;
    } else if (better(v, i, s1, i1)) {
        s2 = s1; i2 = i1;
        s1 = v;  i1 = i;
    } else if (better(v, i, s2, i2)) {
        s2 = v;  i2 = i;
    }
}

// Merge sorted (desc) value triple (b0,b1,b2) into (a0,a1,a2). FMNMX net.
__device__ __forceinline__ void merge3(float& a0, float& a1, float& a2,
                                       float b0, float b1, float b2) {
    float r0 = fmaxf(a0, b0);
    float x  = fminf(a0, b0);
    float y  = fmaxf(a1, b1);
    float z  = fminf(a1, b1);
    float r1 = fmaxf(x, y);
    float s  = fminf(x, y);
    float r2 = fmaxf(fmaxf(s, z), fmaxf(a2, b2));
    a0 = r0; a1 = r1; a2 = r2;
}

__global__ __launch_bounds__(TPB, 4)
void peaks_kernel(const float* __restrict__ x, float* __restrict__ out) {
    const int row = blockIdx.x;
    const float* __restrict__ xr = x + (size_t)row * W;
    const int t   = threadIdx.x;
    const int lid = t & 31;
    const int wid = t >> 5;
    const int start = t * EPT;
    const unsigned fm = 0xffffffffu;

    __shared__ float s_cval[NWARP][WCAP];
    __shared__ int   s_cidx[NWARP][WCAP];
    __shared__ int   s_cnt[NWARP];
    __shared__ float s_tv[NWARP][3];   // per-warp top-3 values (sorted desc)
    __shared__ int   s_ti[NWARP][3];   // per-warp top-3 indices

    if (lid == 0) s_cnt[wid] = 0;

    // ---- Load chunk (4x LDG.128, front-batched) ----
    float c[EPT];
    const float4* p = reinterpret_cast<const float4*>(xr + start);
#pragma unroll
    for (int q = 0; q < EPT / 4; q++) {
        float4 v = p[q];
        c[q * 4 + 0] = v.x;
        c[q * 4 + 1] = v.y;
        c[q * 4 + 2] = v.z;
        c[q * 4 + 3] = v.w;
    }

    // ---- Halo: intra-warp shuffle + 2 predicated scalar loads per warp ----
    float pl = -CUDART_INF_F, pn = -CUDART_INF_F;
    if (lid == 0  && t > 0)        pl = __ldg(xr + start - 1);
    if (lid == 31 && t < TPB - 1)  pn = __ldg(xr + start + EPT);
    float vprev = __shfl_up_sync(fm, c[EPT - 1], 1);
    float vnext = __shfl_down_sync(fm, c[0], 1);
    if (lid == 0)  vprev = pl;
    if (lid == 31) vnext = pn;

    // ---- Phase 1: predicated peak-max, raw c[] preserved ----
    float m0 = -CUDART_INF_F, m1 = -CUDART_INF_F,
          m2 = -CUDART_INF_F, m3 = -CUDART_INF_F;
    {
        float prev = vprev;
#pragma unroll
        for (int j = 0; j < EPT; j++) {
            const float v = c[j];
            const float r = (j == EPT - 1) ? vnext : c[j + 1];
            const float mx = fmaxf(prev, r);
            if (v >= mx) {   // local max (smax==v) <=> v >= max(l,r)
                switch (j & 3) {
                    case 0: m0 = fmaxf(m0, v); break;
                    case 1: m1 = fmaxf(m1, v); break;
                    case 2: m2 = fmaxf(m2, v); break;
                    default: m3 = fmaxf(m3, v); break;
                }
            }
            prev = v;
        }
    }
    const float myMax = fmaxf(fmaxf(m0, m1), fmaxf(m2, m3));

    // ---- Warp-local threshold: 3rd-largest thread-max (value-only tree) ----
    float a0 = myMax, a1 = -CUDART_INF_F, a2 = -CUDART_INF_F;
#pragma unroll
    for (int off = 16; off; off >>= 1) {
        float b0 = __shfl_down_sync(fm, a0, off);
        float b1 = __shfl_down_sync(fm, a1, off);
        float b2 = __shfl_down_sync(fm, a2, off);
        if (lid + off >= 32) { b0 = b1 = b2 = -CUDART_INF_F; }
        merge3(a0, a1, a2, b0, b1, b2);
    }
    const float thr = __shfl_sync(fm, a2, 0);
    __syncwarp(fm);   // order s_cnt[wid]=0 before atomics

    // ---- Phase 2: candidate threads recompute scores, push to warp buffer ----
    if (myMax >= thr) {
        float prev = vprev;
#pragma unroll
        for (int j = 0; j < EPT; j++) {
            const float v = c[j];
            const float r = (j == EPT - 1) ? vnext : c[j + 1];
            const float mx = fmaxf(prev, r);
            const float sc = (v >= mx) ? v : 0.0f;
            // sc > 0 guard: prevents degenerate flood when thr == -inf
            if (sc >= thr && sc > 0.0f) {
                int pos = atomicAdd(&s_cnt[wid], 1);
                if (pos < WCAP) { s_cval[wid][pos] = sc; s_cidx[wid][pos] = start + j; }
            }
            prev = v;
        }
    }
    __syncwarp(fm);

    // ---- Lane 0: exact warp top-3 over tiny candidate list ----
    if (lid == 0) {
        int n = s_cnt[wid]; if (n > WCAP) n = WCAP;
        float s0 = -CUDART_INF_F, s1 = -CUDART_INF_F, s2 = -CUDART_INF_F;
        int   i0 = 0x7fffffff,    i1 = 0x7fffffff,    i2 = 0x7fffffff;
        for (int k = 0; k < n; k++)
            ins3(s_cval[wid][k], s_cidx[wid][k], s0, i0, s1, i1, s2, i2);
        s_tv[wid][0] = s0; s_tv[wid][1] = s1; s_tv[wid][2] = s2;
        s_ti[wid][0] = i0; s_ti[wid][1] = i1; s_ti[wid][2] = i2;
    }
    __syncthreads();   // the ONLY block-wide barrier

    // ---- Warp 0: merge 16 warp triples -> row top-3 -> outputs ----
    if (wid == 0) {
        float s0 = -CUDART_INF_F, s1 = -CUDART_INF_F, s2 = -CUDART_INF_F;
        int   i0 = 0x7fffffff,    i1 = 0x7fffffff,    i2 = 0x7fffffff;
        if (lid < NWARP) {
            s0 = s_tv[lid][0]; s1 = s_tv[lid][1]; s2 = s_tv[lid][2];
            i0 = s_ti[lid][0]; i1 = s_ti[lid][1]; i2 = s_ti[lid][2];
        }
        // lanes >= 16 hold neutral; wrap-corrupted lanes are never consumed
#pragma unroll
        for (int off = 8; off; off >>= 1) {
            float b0 = __shfl_down_sync(fm, s0, off);
            float b1 = __shfl_down_sync(fm, s1, off);
            float b2 = __shfl_down_sync(fm, s2, off);
            int   c0 = __shfl_down_sync(fm, i0, off);
            int   c1 = __shfl_down_sync(fm, i1, off);
            int   c2 = __shfl_down_sync(fm, i2, off);
            ins3(b0, c0, s0, i0, s1, i1, s2, i2);
            ins3(b1, c1, s0, i0, s1, i1, s2, i2);
            ins3(b2, c2, s0, i0, s1, i1, s2, i2);
        }

        if (lid == 0) {
            // Output layout (return order, all fp32):
            //   [0       , ROWS*3) : neighbor_score
            //   [ROWS*3  , ROWS*6) : topk_scores
            //   [ROWS*6  , ROWS*9) : topk_index (int values, exact in fp32)
            const int top = i0;
#pragma unroll
            for (int k = 0; k < 3; k++) {
                int nb = top - 1 + k;
                nb = nb < 0 ? 0 : (nb > W - 1 ? W - 1 : nb);
                out[(size_t)row * 3 + k] = __ldg(xr + nb);
            }
            const float ts[3] = {s0, s1, s2};
            const int   ti[3] = {i0, i1, i2};
#pragma unroll
            for (int k = 0; k < 3; k++) {
                out[(size_t)ROWS * 3 + (size_t)row * 3 + k] = ts[k];
                out[(size_t)ROWS * 6 + (size_t)row * 3 + k] = (float)(ti[k] - NLAG);
            }
        }
    }
}

extern "C" void kernel_launch(void* const* d_in, const int* in_sizes, int n_in,
                              void* d_out, int out_size) {
    const float* x = (const float*)d_in[0];
    float* out = (float*)d_out;
    (void)in_sizes; (void)n_in; (void)out_size;
    peaks_kernel<<<ROWS, TPB>>>(x, out);
}

// round 7
// speedup vs baseline: 1.6494x; 1.6494x over previous
#include <cuda_runtime.h>
#include <math_constants.h>

#define W      8192
#define ROWS   4096      // 16 * 1 * 256
#define NLAG   4096      // W / 2
#define TPB    512
#define EPT    16        // elements per thread (TPB * EPT == W)
#define NWARP  (TPB / 32)
#define CAP    256       // candidate buffer capacity (expected ~3-8 used)

__device__ __forceinline__ bool better(float v, int i, float v2, int i2) {
    return (v > v2) || (v == v2 && i < i2);
}

__device__ __forceinline__ void ins3(float v, int i,
                                     float& s0, int& i0,
                                     float& s1, int& i1,
                                     float& s2, int& i2) {
    if (better(v, i, s0, i0)) {
        s2 = s1; i2 = i1;
        s1 = s0; i1 = i0;
        s0 = v;  i0 = i;
    } else if (better(v, i, s1, i1)) {
        s2 = s1; i2 = i1;
        s1 = v;  i1 = i;
    } else if (better(v, i, s2, i2)) {
        s2 = v;  i2 = i;
    }
}

// Merge sorted (desc) value triple (b0,b1,b2) into (a0,a1,a2). FMNMX net.
__device__ __forceinline__ void merge3(float& a0, float& a1, float& a2,
                                       float b0, float b1, float b2) {
    float r0 = fmaxf(a0, b0);
    float x  = fminf(a0, b0);
    float y  = fmaxf(a1, b1);
    float z  = fminf(a1, b1);
    float r1 = fmaxf(x, y);
    float s  = fminf(x, y);
    float r2 = fmaxf(fmaxf(s, z), fmaxf(a2, b2));
    a0 = r0; a1 = r1; a2 = r2;
}

__global__ __launch_bounds__(TPB, 4)
void peaks_kernel(const float* __restrict__ x, float* __restrict__ out) {
    const int row = blockIdx.x;
    const float* __restrict__ xr = x + (size_t)row * W;
    const int t   = threadIdx.x;
    const int lid = t & 31;
    const int wid = t >> 5;
    const int start = t * EPT;
    const unsigned fm = 0xffffffffu;

    __shared__ float s_wmax[NWARP];
    __shared__ float s_t;
    __shared__ int   s_cnt;
    __shared__ float s_val[CAP];
    __shared__ int   s_idx[CAP];

    if (t == 0) s_cnt = 0;   // ordered before phase-2 atomics by B2+B3

    // ---- Load chunk (4x LDG.128, front-batched) + halo scalar loads ----
    float c[EPT];
    const float4* p = reinterpret_cast<const float4*>(xr + start);
#pragma unroll
    for (int q = 0; q < EPT / 4; q++) {
        float4 v = p[q];
        c[q * 4 + 0] = v.x;
        c[q * 4 + 1] = v.y;
        c[q * 4 + 2] = v.z;
        c[q * 4 + 3] = v.w;
    }
    float pl = -CUDART_INF_F, pn = -CUDART_INF_F;
    if (lid == 0  && t > 0)        pl = __ldg(xr + start - 1);
    if (lid == 31 && t < TPB - 1)  pn = __ldg(xr + start + EPT);

    // ---- Halo: intra-warp shuffle, no block barrier ----
    float vprev = __shfl_up_sync(fm, c[EPT - 1], 1);
    float vnext = __shfl_down_sync(fm, c[0], 1);
    if (lid == 0)  vprev = pl;
    if (lid == 31) vnext = pn;

    // ---- Phase 1: predicated peak-max, raw c[] preserved ----
    float m0 = -CUDART_INF_F, m1 = -CUDART_INF_F,
          m2 = -CUDART_INF_F, m3 = -CUDART_INF_F;
    {
        float prev = vprev;
#pragma unroll
        for (int j = 0; j < EPT; j++) {
            const float v = c[j];
            const float r = (j == EPT - 1) ? vnext : c[j + 1];
            const float mx = fmaxf(prev, r);
            if (v >= mx) {   // local max (smax==v) <=> v >= max(l,r)
                switch (j & 3) {
                    case 0: m0 = fmaxf(m0, v); break;
                    case 1: m1 = fmaxf(m1, v); break;
                    case 2: m2 = fmaxf(m2, v); break;
                    default: m3 = fmaxf(m3, v); break;
                }
            }
            prev = v;
        }
    }
    const float myMax = fmaxf(fmaxf(m0, m1), fmaxf(m2, m3));

    // ---- Plain warp max (cheap; duplicate-tolerant) ----
    float wmax = myMax;
#pragma unroll
    for (int off = 16; off; off >>= 1)
        wmax = fmaxf(wmax, __shfl_down_sync(fm, wmax, off));
    if (lid == 0) s_wmax[wid] = wmax;
    __syncthreads();                                          // B2

    // ---- Warp 0 ONLY: 3rd-largest of 16 warp maxima -> block threshold ----
    // Valid lower bound: top-3 warps each contain one peak >= u2, so the
    // row's 3rd-largest score >= u2.
    if (wid == 0) {
        float u0 = (lid < NWARP) ? s_wmax[lid] : -CUDART_INF_F;
        float u1 = -CUDART_INF_F, u2 = -CUDART_INF_F;
#pragma unroll
        for (int off = 8; off; off >>= 1) {
            float b0 = __shfl_down_sync(fm, u0, off);
            float b1 = __shfl_down_sync(fm, u1, off);
            float b2 = __shfl_down_sync(fm, u2, off);
            merge3(u0, u1, u2, b0, b1, b2);
        }
        if (lid == 0) s_t = u2;
    }
    __syncthreads();                                          // B3

    // ---- Phase 2: candidate threads recompute scores and push (~3/block) ----
    const float thr = s_t;
    if (myMax >= thr) {
        float prev = vprev;
#pragma unroll
        for (int j = 0; j < EPT; j++) {
            const float v = c[j];
            const float r = (j == EPT - 1) ? vnext : c[j + 1];
            const float mx = fmaxf(prev, r);
            const float sc = (v >= mx) ? v : 0.0f;
            // sc > 0 guard: prevents degenerate flood if thr <= 0
            if (sc >= thr && sc > 0.0f) {
                int pos = atomicAdd(&s_cnt, 1);
                if (pos < CAP) { s_val[pos] = sc; s_idx[pos] = start + j; }
            }
            prev = v;
        }
    }
    __syncthreads();                                          // B4

    // ---- Thread 0: exact top-3 over tiny candidate list, then outputs ----
    if (t == 0) {
        int n = s_cnt; if (n > CAP) n = CAP;
        float s0 = -CUDART_INF_F, s1 = -CUDART_INF_F, s2 = -CUDART_INF_F;
        int   i0 = 0x7fffffff,    i1 = 0x7fffffff,    i2 = 0x7fffffff;
        for (int k = 0; k < n; k++)
            ins3(s_val[k], s_idx[k], s0, i0, s1, i1, s2, i2);

        // Output layout (return order, all fp32):
        //   [0       , ROWS*3) : neighbor_score
        //   [ROWS*3  , ROWS*6) : topk_scores
        //   [ROWS*6  , ROWS*9) : topk_index (int values, exact in fp32)
        const int top = i0;
#pragma unroll
        for (int k = 0; k < 3; k++) {
            int nb = top - 1 + k;
            nb = nb < 0 ? 0 : (nb > W - 1 ? W - 1 : nb);
            out[(size_t)row * 3 + k] = __ldg(xr + nb);
        }
        const float ts[3] = {s0, s1, s2};
        const int   ti[3] = {i0, i1, i2};
#pragma unroll
        for (int k = 0; k < 3; k++) {
            out[(size_t)ROWS * 3 + (size_t)row * 3 + k] = ts[k];
            out[(size_t)ROWS * 6 + (size_t)row * 3 + k] = (float)(ti[k] - NLAG);
        }
    }
}

extern "C" void kernel_launch(void* const* d_in, const int* in_sizes, int n_in,
                              void* d_out, int out_size) {
    const float* x = (const float*)d_in[0];
    float* out = (float*)d_out;
    (void)in_sizes; (void)n_in; (void)out_size;
    peaks_kernel<<<ROWS, TPB>>>(x, out);
}